// round 4
// baseline (speedup 1.0000x reference)
#include <cuda_runtime.h>
#include <cstdint>

#define NROW 8192
#define DIM  512
#define KSEL 49
#define K3   1536            /* 3-term split: A=[hi,lo,hi], B=[hi,hi,lo] */
#define KB   32              /* floats per pipeline chunk */
#define NCH  (K3/KB)         /* 48 */
#define STAGES 3
#define TMt  128
#define TNt  256
#define ASTR 36              /* padded smem row stride (floats) */
#define A_BYTES (128*ASTR*4)           /* 18432 */
#define B_BYTES (256*ASTR*4)           /* 36864 */
#define STAGE_BYTES (A_BYTES + B_BYTES)/* 55296 */
#define SMEM_BYTES (STAGES*STAGE_BYTES)/* 165888; transpose buf 135168 fits */

// ---------------- scratch ----------------
__device__ float g_Wc[DIM*DIM];
__device__ float g_bc[DIM];
__device__ float g_E [(size_t)NROW*DIM];
__device__ float g_Q3a[(size_t)NROW*K3];
__device__ float g_W3b[(size_t)DIM*K3];
__device__ float g_E3a[(size_t)NROW*K3];
__device__ float g_E3b[(size_t)NROW*K3];
__device__ float g_C [(size_t)NROW*NROW];

// ---------------- helpers ----------------
__device__ __forceinline__ uint32_t smem_u32(const void* p) {
    uint32_t a;
    asm("{ .reg .u64 t; cvta.to.shared.u64 t, %1; cvt.u32.u64 %0, t; }" : "=r"(a) : "l"(p));
    return a;
}
__device__ __forceinline__ void cp16(uint32_t dst, const void* src) {
    asm volatile("cp.async.cg.shared.global [%0], [%1], 16;" :: "r"(dst), "l"(src));
}
#define CP_COMMIT() asm volatile("cp.async.commit_group;")
#define CP_WAIT(n)  asm volatile("cp.async.wait_group %0;" :: "n"(n))

#define MMA8(d, a, b) \
    asm volatile("mma.sync.aligned.m16n8k8.row.col.f32.tf32.tf32.f32 " \
        "{%0,%1,%2,%3}, {%4,%5,%6,%7}, {%8,%9}, {%0,%1,%2,%3};" \
        : "+f"((d)[0]), "+f"((d)[1]), "+f"((d)[2]), "+f"((d)[3]) \
        : "r"(__float_as_uint((a)[0])), "r"(__float_as_uint((a)[1])), \
          "r"(__float_as_uint((a)[2])), "r"(__float_as_uint((a)[3])), \
          "r"(__float_as_uint((b)[0])), "r"(__float_as_uint((b)[1])))

__device__ __forceinline__ float tf32r(float x) {
    uint32_t r; asm("cvt.rna.tf32.f32 %0, %1;" : "=r"(r) : "f"(x));
    return __uint_as_float(r);
}
__device__ __forceinline__ unsigned int enc_key(float f) {
    unsigned int u = __float_as_uint(f);
    return (u & 0x80000000u) ? ~u : (u | 0x80000000u);
}
__device__ __forceinline__ float dec_key(unsigned int k) {
    return (k & 0x80000000u) ? __uint_as_float(k & 0x7fffffffu) : __uint_as_float(~k);
}

// ---------------- kernel: softmax + combine 4 projections ----------------
__global__ void k_combine(const float* __restrict__ sw,
    const float* __restrict__ W0, const float* __restrict__ W1,
    const float* __restrict__ W2, const float* __restrict__ W3,
    const float* __restrict__ b0, const float* __restrict__ b1,
    const float* __restrict__ b2, const float* __restrict__ b3)
{
    float a0 = sw[0], a1 = sw[1], a2 = sw[2], a3 = sw[3];
    float m  = fmaxf(fmaxf(a0, a1), fmaxf(a2, a3));
    float e0 = expf(a0 - m), e1 = expf(a1 - m), e2 = expf(a2 - m), e3 = expf(a3 - m);
    float inv = 1.0f / (e0 + e1 + e2 + e3);
    float w0 = e0 * inv, w1 = e1 * inv, w2 = e2 * inv, w3 = e3 * inv;
    int i = blockIdx.x * blockDim.x + threadIdx.x;
    if (i < DIM * DIM)
        g_Wc[i] = w0 * W0[i] + w1 * W1[i] + w2 * W2[i] + w3 * W3[i];
    if (i < DIM)
        g_bc[i] = w0 * b0[i] + w1 * b1[i] + w2 * b2[i] + w3 * b3[i];
}

// ---------------- kernel: 3-term split. A: [hi,lo,hi]  B: [hi,hi,lo] ----------------
__global__ void k_split(const float4* __restrict__ src,
                        float4* __restrict__ dA, float4* __restrict__ dB,
                        int n4)
{
    int i = blockIdx.x * blockDim.x + threadIdx.x;
    if (i >= n4) return;
    float4 s = src[i];
    float h0 = tf32r(s.x), l0 = tf32r(s.x - h0);
    float h1 = tf32r(s.y), l1 = tf32r(s.y - h1);
    float h2 = tf32r(s.z), l2 = tf32r(s.z - h2);
    float h3 = tf32r(s.w), l3 = tf32r(s.w - h3);
    if (dA) {
        dA[i*3+0] = make_float4(h0, l0, h0, h1);
        dA[i*3+1] = make_float4(l1, h1, h2, l2);
        dA[i*3+2] = make_float4(h2, h3, l3, h3);
    }
    if (dB) {
        dB[i*3+0] = make_float4(h0, h0, l0, h1);
        dB[i*3+1] = make_float4(h1, l1, h2, h2);
        dB[i*3+2] = make_float4(l2, h3, h3, l3);
    }
}

// ---------------- shared tf32 mma mainloop ----------------
struct GemmCtx {
    int wm, wn, g, tg;
    float acc[4][8][4];
};

__device__ __forceinline__ void load_stage(char* smem, int slot, int k0,
                                           const float* A, const float* B,
                                           int rowBase, int colBase)
{
    const int tid = threadIdx.x;
    uint32_t base = smem_u32(smem) + slot * STAGE_BYTES;
    #pragma unroll
    for (int u = 0; u < 4; u++) {
        int id = tid + 256*u, row = id >> 3, cc = id & 7;
        cp16(base + row*144 + cc*16, A + (size_t)(rowBase+row)*K3 + k0 + cc*4);
    }
    #pragma unroll
    for (int u = 0; u < 8; u++) {
        int id = tid + 256*u, row = id >> 3, cc = id & 7;
        cp16(base + A_BYTES + row*144 + cc*16, B + (size_t)(colBase+row)*K3 + k0 + cc*4);
    }
}

__device__ __forceinline__ void gemm_main(char* smem, GemmCtx& cx,
                                          const float* A, const float* B,
                                          int rowBase, int colBase)
{
    const int tid = threadIdx.x, wid = tid >> 5, lane = tid & 31;
    cx.wm = wid >> 2; cx.wn = wid & 3;
    cx.g = lane >> 2; cx.tg = lane & 3;
    #pragma unroll
    for (int ma = 0; ma < 4; ma++)
        #pragma unroll
        for (int na = 0; na < 8; na++)
            #pragma unroll
            for (int q = 0; q < 4; q++) cx.acc[ma][na][q] = 0.f;

    load_stage(smem, 0, 0, A, B, rowBase, colBase); CP_COMMIT();
    load_stage(smem, 1, KB, A, B, rowBase, colBase); CP_COMMIT();

    #pragma unroll 1
    for (int t = 0; t < NCH; t++) {
        CP_WAIT(STAGES - 2);
        __syncthreads();
        int pf = t + STAGES - 1;
        if (pf < NCH) load_stage(smem, pf % STAGES, pf * KB, A, B, rowBase, colBase);
        CP_COMMIT();

        const float* sA = (const float*)(smem + (t % STAGES) * STAGE_BYTES);
        const float* sB = (const float*)(smem + (t % STAGES) * STAGE_BYTES + A_BYTES);
        #pragma unroll
        for (int ks = 0; ks < KB/8; ks++) {
            float af[4][4], bf[8][2];
            #pragma unroll
            for (int ma = 0; ma < 4; ma++) {
                const float* p = sA + (cx.wm*64 + ma*16 + cx.g)*ASTR + ks*8 + cx.tg;
                af[ma][0] = p[0]; af[ma][1] = p[8*ASTR];
                af[ma][2] = p[4]; af[ma][3] = p[8*ASTR + 4];
            }
            #pragma unroll
            for (int na = 0; na < 8; na++) {
                const float* p = sB + (cx.wn*64 + na*8 + cx.g)*ASTR + ks*8 + cx.tg;
                bf[na][0] = p[0]; bf[na][1] = p[4];
            }
            #pragma unroll
            for (int ma = 0; ma < 4; ma++)
                #pragma unroll
                for (int na = 0; na < 8; na++)
                    MMA8(cx.acc[ma][na], af[ma], bf[na]);
        }
        __syncthreads();
    }
}

// ---------------- kernel: E = Q @ Wc^T + bc ----------------
__global__ __launch_bounds__(256, 1) void k_gemmE()
{
    extern __shared__ char smem[];
    const int rowBase = blockIdx.y * TMt, colBase = blockIdx.x * TNt;
    GemmCtx cx;
    gemm_main(smem, cx, g_Q3a, g_W3b, rowBase, colBase);

    #pragma unroll
    for (int ma = 0; ma < 4; ma++) {
        int r = rowBase + cx.wm*64 + ma*16 + cx.g;
        #pragma unroll
        for (int na = 0; na < 8; na++) {
            int c = colBase + cx.wn*64 + na*8 + cx.tg*2;
            float2 bias = *(const float2*)&g_bc[c];
            *(float2*)&g_E[(size_t)r*DIM + c] =
                make_float2(cx.acc[ma][na][0] + bias.x, cx.acc[ma][na][1] + bias.y);
            *(float2*)&g_E[(size_t)(r+8)*DIM + c] =
                make_float2(cx.acc[ma][na][2] + bias.x, cx.acc[ma][na][3] + bias.y);
        }
    }
}

// ---------------- kernel: L2-normalize rows of E ----------------
__global__ void k_norm()
{
    const int row = blockIdx.x, tid = threadIdx.x;  // 128 threads
    float4* e = (float4*)(g_E + (size_t)row * DIM);
    float4 v = e[tid];
    float ss = v.x*v.x + v.y*v.y + v.z*v.z + v.w*v.w;
    #pragma unroll
    for (int o = 16; o > 0; o >>= 1) ss += __shfl_xor_sync(0xffffffffu, ss, o);
    __shared__ float sred[4];
    if ((tid & 31) == 0) sred[tid >> 5] = ss;
    __syncthreads();
    float tot = sred[0] + sred[1] + sred[2] + sred[3];
    float s = 1.0f / fmaxf(sqrtf(tot), 1e-12f);
    v.x *= s; v.y *= s; v.z *= s; v.w *= s;
    e[tid] = v;
}

// ---------------- kernel: symmetric C = E E^T, upper tiles + mirrored transpose ----------------
__global__ __launch_bounds__(256, 1) void k_symgemm()
{
    extern __shared__ char smem[];
    // tile id -> (i, j), i <= 2j+1 ; prefix(j) = j^2 + j
    int t = blockIdx.x;
    int j = (int)((sqrtf(4.0f * (float)t + 1.0f) - 1.0f) * 0.5f);
    while ((j + 1) * (j + 1) + (j + 1) <= t) j++;
    while (j * j + j > t) j--;
    const int i = t - (j * j + j);
    const int rowBase = i * TMt, colBase = j * TNt;

    GemmCtx cx;
    gemm_main(smem, cx, g_E3a, g_E3b, rowBase, colBase);

    // direct stores (row-major, coalesced 32B runs)
    #pragma unroll
    for (int ma = 0; ma < 4; ma++) {
        int r = rowBase + cx.wm*64 + ma*16 + cx.g;
        #pragma unroll
        for (int na = 0; na < 8; na++) {
            int c = colBase + cx.wn*64 + na*8 + cx.tg*2;
            *(float2*)&g_C[(size_t)r*NROW + c] =
                make_float2(cx.acc[ma][na][0], cx.acc[ma][na][1]);
            *(float2*)&g_C[(size_t)(r+8)*NROW + c] =
                make_float2(cx.acc[ma][na][2], cx.acc[ma][na][3]);
        }
    }

    // transpose via smem, then coalesced mirror stores
    __syncthreads();
    float* T = (float*)smem;                 // [256][132]
    #pragma unroll
    for (int ma = 0; ma < 4; ma++) {
        int rl = cx.wm*64 + ma*16 + cx.g;
        #pragma unroll
        for (int na = 0; na < 8; na++) {
            int cl = cx.wn*64 + na*8 + cx.tg*2;
            T[(size_t)cl*132 + rl]       = cx.acc[ma][na][0];
            T[(size_t)(cl+1)*132 + rl]   = cx.acc[ma][na][1];
            T[(size_t)cl*132 + rl+8]     = cx.acc[ma][na][2];
            T[(size_t)(cl+1)*132 + rl+8] = cx.acc[ma][na][3];
        }
    }
    __syncthreads();
    const int wid = threadIdx.x >> 5, lane = threadIdx.x & 31;
    for (int rr = wid; rr < 256; rr += 8) {
        float4 v = *(const float4*)&T[(size_t)rr*132 + lane*4];
        *(float4*)&g_C[(size_t)(colBase + rr)*NROW + rowBase + lane*4] = v;
    }
}

// ---------------- kernel: zero output ----------------
__global__ void k_zero(float4* __restrict__ out)
{
    const size_t n4 = (size_t)NROW * NROW / 4;
    const size_t stride = (size_t)gridDim.x * blockDim.x;
    for (size_t i = (size_t)blockIdx.x * blockDim.x + threadIdx.x; i < n4; i += stride)
        out[i] = make_float4(0.f, 0.f, 0.f, 0.f);
}

// ---------------- kernel: per-row exact top-49 + symmetric scatter ----------------
__global__ __launch_bounds__(256) void k_topk(float* __restrict__ out)
{
    __shared__ unsigned int sk[NROW];
    __shared__ unsigned int hist[256];
    __shared__ unsigned int s_pval;
    __shared__ int s_krem;
    __shared__ int s_nsel;

    const int row = blockIdx.x, tid = threadIdx.x, lane = tid & 31;
    const float* crow = g_C + (size_t)row * NROW;

    for (int v = tid; v < NROW / 4; v += 256) {
        float4 f = *(const float4*)(crow + v * 4);
        int c = v * 4;
        sk[c + 0] = enc_key(f.x); sk[c + 1] = enc_key(f.y);
        sk[c + 2] = enc_key(f.z); sk[c + 3] = enc_key(f.w);
    }
    __syncthreads();
    if (tid == 0) { sk[row] = 0u; s_pval = 0u; s_krem = KSEL; s_nsel = 0; }
    __syncthreads();

    #pragma unroll
    for (int lvl = 0; lvl < 4; lvl++) {
        const int sh = 24 - 8 * lvl;
        hist[tid] = 0u;
        __syncthreads();
        const unsigned int pv = s_pval;
        const unsigned int pm = (lvl == 0) ? 0u : (0xFFFFFFFFu << (32 - 8 * lvl));
        for (int c = tid; c < NROW; c += 256) {
            unsigned int k = sk[c];
            bool ok = (k & pm) == pv;
            unsigned int bin = ok ? ((k >> sh) & 255u) : 0xffffffffu;
            unsigned int mm = __match_any_sync(0xffffffffu, bin);
            if (ok && ((__ffs(mm) - 1) == lane))
                atomicAdd(&hist[bin], __popc(mm));
        }
        __syncthreads();
        if (tid == 0) {
            int kr = s_krem;
            int b = 255;
            for (;; b--) {
                int cnt = (int)hist[b];
                if (kr <= cnt || b == 0) break;
                kr -= cnt;
            }
            s_krem = kr;
            s_pval = pv | ((unsigned int)b << sh);
        }
        __syncthreads();
    }

    const unsigned int Kth = s_pval;
    for (int c = tid; c < NROW; c += 256) {
        unsigned int k = sk[c];
        if (k > Kth) {
            atomicAdd(&s_nsel, 1);
            float val = dec_key(k);
            out[(size_t)row * NROW + c] = val;
            out[(size_t)c * NROW + row] = val;
        }
    }
    __syncthreads();
    const float kval = dec_key(Kth);
    for (int c = tid; c < NROW; c += 256) {
        if (sk[c] == Kth) {
            int p = atomicAdd(&s_nsel, 1);
            if (p < KSEL) {
                out[(size_t)row * NROW + c] = kval;
                out[(size_t)c * NROW + row] = kval;
            }
        }
    }
    if (tid == 0) out[(size_t)row * NROW + row] = 1.0f;
}

// ---------------- launcher ----------------
extern "C" void kernel_launch(void* const* d_in, const int* in_sizes, int n_in,
                              void* d_out, int out_size)
{
    (void)in_sizes; (void)n_in; (void)out_size;
    const float* Q  = (const float*)d_in[0];
    const float* sw = (const float*)d_in[1];

    cudaFuncSetAttribute(k_gemmE,   cudaFuncAttributeMaxDynamicSharedMemorySize, SMEM_BYTES);
    cudaFuncSetAttribute(k_symgemm, cudaFuncAttributeMaxDynamicSharedMemorySize, SMEM_BYTES);

    void *pWc, *pE, *pQ3a, *pW3b, *pE3a, *pE3b;
    cudaGetSymbolAddress(&pWc,  g_Wc);
    cudaGetSymbolAddress(&pE,   g_E);
    cudaGetSymbolAddress(&pQ3a, g_Q3a);
    cudaGetSymbolAddress(&pW3b, g_W3b);
    cudaGetSymbolAddress(&pE3a, g_E3a);
    cudaGetSymbolAddress(&pE3b, g_E3b);

    k_combine<<<(DIM * DIM + 255) / 256, 256>>>(sw,
        (const float*)d_in[2], (const float*)d_in[4],
        (const float*)d_in[6], (const float*)d_in[8],
        (const float*)d_in[3], (const float*)d_in[5],
        (const float*)d_in[7], (const float*)d_in[9]);

    k_zero<<<4096, 256>>>((float4*)d_out);

    // splits: Q -> A-pattern, Wc -> B-pattern
    {
        int n4 = NROW * DIM / 4;
        k_split<<<(n4 + 255) / 256, 256>>>((const float4*)Q, (float4*)pQ3a, nullptr, n4);
        int m4 = DIM * DIM / 4;
        k_split<<<(m4 + 255) / 256, 256>>>((const float4*)pWc, nullptr, (float4*)pW3b, m4);
    }

    dim3 ge(DIM / TNt, NROW / TMt);   // (2, 64)
    k_gemmE<<<ge, 256, SMEM_BYTES>>>();

    k_norm<<<NROW, 128>>>();

    {
        int n4 = NROW * DIM / 4;
        k_split<<<(n4 + 255) / 256, 256>>>((const float4*)pE, (float4*)pE3a, (float4*)pE3b, n4);
    }

    k_symgemm<<<1056, 256, SMEM_BYTES>>>();   // upper-tri 128x256 tiles

    k_topk<<<NROW, 256>>>((float*)d_out);
}

// round 5
// speedup vs baseline: 1.3232x; 1.3232x over previous
#include <cuda_runtime.h>
#include <cuda_bf16.h>
#include <cstdint>

#define NROW 8192
#define DIM  512
#define KSEL 49

/* ---- fp32 SIMT gemmE (R1 core) ---- */
#define TILE 128
#define KT   16
#define SPAD 132

/* ---- bf16 3-term symgemm ---- */
#define K3B  3072              /* bytes per row: 1536 bf16 */
#define CHB  128               /* chunk bytes = 64 bf16 */
#define NCH  24                /* K3B / CHB */
#define ROWB 144               /* padded smem row bytes (conflict-free ldmatrix) */
#define STG_BYTES (2*128*ROWB) /* A + B tiles = 36864 */
#define SMEM_SYM  (3*STG_BYTES)/* 110592 */

#define MARGIN 5e-4f
#define CAP    1024

// ---------------- scratch ----------------
__device__ float g_Wc[DIM*DIM];
__device__ float g_bc[DIM];
__device__ float g_E [(size_t)NROW*DIM];
__device__ unsigned char g_Eb3a[(size_t)NROW*K3B];
__device__ unsigned char g_Eb3b[(size_t)NROW*K3B];
__device__ float g_C [(size_t)NROW*NROW];

// ---------------- helpers ----------------
__device__ __forceinline__ uint32_t smem_u32(const void* p) {
    uint32_t a;
    asm("{ .reg .u64 t; cvta.to.shared.u64 t, %1; cvt.u32.u64 %0, t; }" : "=r"(a) : "l"(p));
    return a;
}
__device__ __forceinline__ void cp16(uint32_t dst, const void* src) {
    asm volatile("cp.async.cg.shared.global [%0], [%1], 16;" :: "r"(dst), "l"(src));
}
#define CP_COMMIT() asm volatile("cp.async.commit_group;")
#define CP_WAIT(n)  asm volatile("cp.async.wait_group %0;" :: "n"(n))

#define LDSM4(r, addr) \
    asm volatile("ldmatrix.sync.aligned.m8n8.x4.shared.b16 {%0,%1,%2,%3}, [%4];" \
        : "=r"((r)[0]), "=r"((r)[1]), "=r"((r)[2]), "=r"((r)[3]) : "r"(addr))

#define MMABF(d, a, b0v, b1v) \
    asm volatile("mma.sync.aligned.m16n8k16.row.col.f32.bf16.bf16.f32 " \
        "{%0,%1,%2,%3}, {%4,%5,%6,%7}, {%8,%9}, {%0,%1,%2,%3};" \
        : "+f"((d)[0]), "+f"((d)[1]), "+f"((d)[2]), "+f"((d)[3]) \
        : "r"((a)[0]), "r"((a)[1]), "r"((a)[2]), "r"((a)[3]), "r"(b0v), "r"(b1v))

// packed f32x2 helpers (fp32 gemmE)
__device__ __forceinline__ unsigned long long ffma2(unsigned long long a,
                                                    unsigned long long b,
                                                    unsigned long long c) {
    unsigned long long d;
    asm("fma.rn.f32x2 %0, %1, %2, %3;" : "=l"(d) : "l"(a), "l"(b), "l"(c));
    return d;
}
__device__ __forceinline__ unsigned long long dup2(float x) {
    unsigned long long r; unsigned int u = __float_as_uint(x);
    asm("mov.b64 %0, {%1, %1};" : "=l"(r) : "r"(u));
    return r;
}
__device__ __forceinline__ unsigned long long pk2(float x, float y) {
    unsigned long long r;
    unsigned int ux = __float_as_uint(x), uy = __float_as_uint(y);
    asm("mov.b64 %0, {%1, %2};" : "=l"(r) : "r"(ux), "r"(uy));
    return r;
}
__device__ __forceinline__ float2 unpk(unsigned long long v) {
    unsigned int lo, hi;
    asm("mov.b64 {%0, %1}, %2;" : "=r"(lo), "=r"(hi) : "l"(v));
    float2 f; f.x = __uint_as_float(lo); f.y = __uint_as_float(hi);
    return f;
}
__device__ __forceinline__ unsigned int enc_key(float f) {
    unsigned int u = __float_as_uint(f);
    return (u & 0x80000000u) ? ~u : (u | 0x80000000u);
}
__device__ __forceinline__ float dec_key(unsigned int k) {
    return (k & 0x80000000u) ? __uint_as_float(k & 0x7fffffffu) : __uint_as_float(~k);
}
__device__ __forceinline__ uint32_t packbf(__nv_bfloat16 lo, __nv_bfloat16 hi) {
    return (uint32_t)__bfloat16_as_ushort(lo) | ((uint32_t)__bfloat16_as_ushort(hi) << 16);
}

// ---------------- kernel: softmax + combine 4 projections ----------------
__global__ void k_combine(const float* __restrict__ sw,
    const float* __restrict__ W0, const float* __restrict__ W1,
    const float* __restrict__ W2, const float* __restrict__ W3,
    const float* __restrict__ b0, const float* __restrict__ b1,
    const float* __restrict__ b2, const float* __restrict__ b3)
{
    float a0 = sw[0], a1 = sw[1], a2 = sw[2], a3 = sw[3];
    float m  = fmaxf(fmaxf(a0, a1), fmaxf(a2, a3));
    float e0 = expf(a0 - m), e1 = expf(a1 - m), e2 = expf(a2 - m), e3 = expf(a3 - m);
    float inv = 1.0f / (e0 + e1 + e2 + e3);
    float w0 = e0 * inv, w1 = e1 * inv, w2 = e2 * inv, w3 = e3 * inv;
    int i = blockIdx.x * blockDim.x + threadIdx.x;
    if (i < DIM * DIM)
        g_Wc[i] = w0 * W0[i] + w1 * W1[i] + w2 * W2[i] + w3 * W3[i];
    if (i < DIM)
        g_bc[i] = w0 * b0[i] + w1 * b1[i] + w2 * b2[i] + w3 * b3[i];
}

// ---------------- fp32 SIMT gemm core (R1, proven) ----------------
template<int KDIM>
__device__ __forceinline__ void gemm_core(const float* __restrict__ A,
                                          const float* __restrict__ B,
                                          int rowBase, int colBase,
                                          int lda, int ldb,
                                          unsigned long long (&acc)[8][4])
{
    __shared__ float As[2][KT][SPAD];
    __shared__ float Bs[2][KT][SPAD];
    const int tid = threadIdx.x;
    const int tx = tid & 15, ty = tid >> 4;
    const int ri0 = ty * 8;
    const int c0  = tx * 4;
    float4 ra[2], rb[2];

    #pragma unroll
    for (int i = 0; i < 8; i++)
        #pragma unroll
        for (int j = 0; j < 4; j++) acc[i][j] = 0ull;

    auto loadG = [&](int k0) {
        #pragma unroll
        for (int l = 0; l < 2; l++) {
            int li = tid * 2 + l;
            int row = li >> 2, q = li & 3;
            ra[l] = *(const float4*)(A + (size_t)(rowBase + row) * lda + k0 + q * 4);
            rb[l] = *(const float4*)(B + (size_t)(colBase + row) * ldb + k0 + q * 4);
        }
    };
    auto storeS = [&](int buf) {
        #pragma unroll
        for (int l = 0; l < 2; l++) {
            int li = tid * 2 + l;
            int row = li >> 2, q = li & 3;
            As[buf][q*4+0][row] = ra[l].x; As[buf][q*4+1][row] = ra[l].y;
            As[buf][q*4+2][row] = ra[l].z; As[buf][q*4+3][row] = ra[l].w;
            Bs[buf][q*4+0][row] = rb[l].x; Bs[buf][q*4+1][row] = rb[l].y;
            Bs[buf][q*4+2][row] = rb[l].z; Bs[buf][q*4+3][row] = rb[l].w;
        }
    };

    loadG(0);
    storeS(0);
    __syncthreads();

    const int nk = KDIM / KT;
    for (int t = 0; t < nk; t++) {
        int buf = t & 1;
        if (t + 1 < nk) loadG((t + 1) * KT);
        #pragma unroll
        for (int kk = 0; kk < KT; kk++) {
            float4 a0 = *(const float4*)&As[buf][kk][ri0];
            float4 a1 = *(const float4*)&As[buf][kk][ri0 + 4];
            float4 b0 = *(const float4*)&Bs[buf][kk][c0];
            float4 b1 = *(const float4*)&Bs[buf][kk][64 + c0];
            unsigned long long bp[4];
            bp[0] = pk2(b0.x, b0.y); bp[1] = pk2(b0.z, b0.w);
            bp[2] = pk2(b1.x, b1.y); bp[3] = pk2(b1.z, b1.w);
            float av[8] = {a0.x, a0.y, a0.z, a0.w, a1.x, a1.y, a1.z, a1.w};
            #pragma unroll
            for (int i = 0; i < 8; i++) {
                unsigned long long ad = dup2(av[i]);
                #pragma unroll
                for (int j = 0; j < 4; j++)
                    acc[i][j] = ffma2(ad, bp[j], acc[i][j]);
            }
        }
        if (t + 1 < nk) storeS((t + 1) & 1);
        __syncthreads();
    }
}

// ---------------- kernel: E = Q @ Wc^T + bc (fp32 exact) ----------------
__global__ __launch_bounds__(256, 2) void k_gemmE(const float* __restrict__ Q)
{
    const int rowBase = blockIdx.y * TILE, colBase = blockIdx.x * TILE;
    unsigned long long acc[8][4];
    gemm_core<DIM>(Q, g_Wc, rowBase, colBase, DIM, DIM, acc);

    const int tid = threadIdx.x, tx = tid & 15, ty = tid >> 4;
    const int ri0 = ty * 8, c0 = tx * 4;
    float4 bias0 = *(const float4*)&g_bc[colBase + c0];
    float4 bias1 = *(const float4*)&g_bc[colBase + 64 + c0];
    #pragma unroll
    for (int i = 0; i < 8; i++) {
        float2 p0 = unpk(acc[i][0]), p1 = unpk(acc[i][1]);
        float2 p2 = unpk(acc[i][2]), p3 = unpk(acc[i][3]);
        size_t rbase = (size_t)(rowBase + ri0 + i) * DIM;
        *(float4*)(g_E + rbase + colBase + c0) =
            make_float4(p0.x + bias0.x, p0.y + bias0.y, p1.x + bias0.z, p1.y + bias0.w);
        *(float4*)(g_E + rbase + colBase + 64 + c0) =
            make_float4(p2.x + bias1.x, p2.y + bias1.y, p3.x + bias1.z, p3.y + bias1.w);
    }
}

// ---------------- kernel: L2-normalize rows of E ----------------
__global__ void k_norm()
{
    const int row = blockIdx.x, tid = threadIdx.x;  // 128 threads
    float4* e = (float4*)(g_E + (size_t)row * DIM);
    float4 v = e[tid];
    float ss = v.x*v.x + v.y*v.y + v.z*v.z + v.w*v.w;
    #pragma unroll
    for (int o = 16; o > 0; o >>= 1) ss += __shfl_xor_sync(0xffffffffu, ss, o);
    __shared__ float sred[4];
    if ((tid & 31) == 0) sred[tid >> 5] = ss;
    __syncthreads();
    float tot = sred[0] + sred[1] + sred[2] + sred[3];
    float s = 1.0f / fmaxf(sqrtf(tot), 1e-12f);
    v.x *= s; v.y *= s; v.z *= s; v.w *= s;
    e[tid] = v;
}

// ---------------- kernel: bf16 3-term split. A=[h,l,h], B=[h,h,l] ----------------
__global__ void k_splitbf()
{
    int i = blockIdx.x * blockDim.x + threadIdx.x;   // one float4 (4 elems)
    if (i >= NROW * DIM / 4) return;
    float4 s = ((const float4*)g_E)[i];

    __nv_bfloat16 h[4], l[4];
    float x[4] = {s.x, s.y, s.z, s.w};
    #pragma unroll
    for (int q = 0; q < 4; q++) {
        h[q] = __float2bfloat16_rn(x[q]);
        l[q] = __float2bfloat16_rn(x[q] - __bfloat162float(h[q]));
    }
    // A pattern: h0,l0,h0, h1,l1,h1, h2,l2,h2, h3,l3,h3
    uint2 a0 = make_uint2(packbf(h[0], l[0]), packbf(h[0], h[1]));
    uint2 a1 = make_uint2(packbf(l[1], h[1]), packbf(h[2], l[2]));
    uint2 a2 = make_uint2(packbf(h[2], h[3]), packbf(l[3], h[3]));
    // B pattern: h0,h0,l0, h1,h1,l1, h2,h2,l2, h3,h3,l3
    uint2 b0 = make_uint2(packbf(h[0], h[0]), packbf(l[0], h[1]));
    uint2 b1 = make_uint2(packbf(h[1], l[1]), packbf(h[2], h[2]));
    uint2 b2 = make_uint2(packbf(l[2], h[3]), packbf(h[3], l[3]));

    uint2* pa = (uint2*)(g_Eb3a + 24 * (size_t)i);
    uint2* pb = (uint2*)(g_Eb3b + 24 * (size_t)i);
    pa[0] = a0; pa[1] = a1; pa[2] = a2;
    pb[0] = b0; pb[1] = b1; pb[2] = b2;
}

// ---------------- kernel: approx C = Eb3a @ Eb3b^T, upper 128x128 tiles + mirror ----------------
__global__ __launch_bounds__(256, 2) void k_symgemm_bf()
{
    extern __shared__ char smem[];
    // tile id -> (i, j), i <= j over 64x64 grid; prefix(j) = j(j+1)/2
    int t = blockIdx.x;
    int j = (int)((sqrtf(8.0f * (float)t + 1.0f) - 1.0f) * 0.5f);
    while ((j + 1) * (j + 2) / 2 <= t) j++;
    while (j * (j + 1) / 2 > t) j--;
    const int i = t - j * (j + 1) / 2;
    const int rowBase = i * TILE, colBase = j * TILE;

    const uint32_t sb = smem_u32(smem);
    const int tid = threadIdx.x, wid = tid >> 5, lane = tid & 31;
    const int wm = wid >> 2, wn = wid & 3;          // warp grid 2x4, warptile 64x32
    const int sel = lane >> 3, tl = lane & 7;

    const unsigned char* __restrict__ Ea = g_Eb3a;
    const unsigned char* __restrict__ Eb = g_Eb3b;

    auto load_stage = [&](int slot, int ch) {
        uint32_t base = sb + slot * STG_BYTES;
        #pragma unroll
        for (int u = 0; u < 4; u++) {
            int id = tid + 256 * u, row = id >> 3, cc = id & 7;
            cp16(base + row * ROWB + cc * 16,
                 Ea + (size_t)(rowBase + row) * K3B + ch * CHB + cc * 16);
        }
        #pragma unroll
        for (int u = 0; u < 4; u++) {
            int id = tid + 256 * u, row = id >> 3, cc = id & 7;
            cp16(base + 128 * ROWB + row * ROWB + cc * 16,
                 Eb + (size_t)(colBase + row) * K3B + ch * CHB + cc * 16);
        }
    };

    // ldmatrix per-lane offsets (within stage)
    uint32_t aoff[4], boff[2];
    #pragma unroll
    for (int ma = 0; ma < 4; ma++)
        aoff[ma] = (uint32_t)((wm*64 + ma*16 + ((sel & 1) << 3) + tl) * ROWB + ((sel >> 1) << 4));
    #pragma unroll
    for (int np = 0; np < 2; np++)
        boff[np] = (uint32_t)(128*ROWB + (wn*32 + np*16 + ((sel >> 1) << 3) + tl) * ROWB + ((sel & 1) << 4));

    float acc[4][4][4];
    #pragma unroll
    for (int ma = 0; ma < 4; ma++)
        #pragma unroll
        for (int na = 0; na < 4; na++)
            #pragma unroll
            for (int q = 0; q < 4; q++) acc[ma][na][q] = 0.f;

    load_stage(0, 0); CP_COMMIT();
    load_stage(1, 1); CP_COMMIT();

    #pragma unroll 1
    for (int ch = 0; ch < NCH; ch++) {
        CP_WAIT(1);
        __syncthreads();
        if (ch + 2 < NCH) load_stage((ch + 2) % 3, ch + 2);
        CP_COMMIT();

        uint32_t sbase = sb + (ch % 3) * STG_BYTES;
        #pragma unroll
        for (int kk = 0; kk < 4; kk++) {
            uint32_t a[4][4], b[2][4];
            #pragma unroll
            for (int ma = 0; ma < 4; ma++) LDSM4(a[ma], sbase + aoff[ma] + kk * 32);
            #pragma unroll
            for (int np = 0; np < 2; np++) LDSM4(b[np], sbase + boff[np] + kk * 32);
            #pragma unroll
            for (int ma = 0; ma < 4; ma++) {
                MMABF(acc[ma][0], a[ma], b[0][0], b[0][1]);
                MMABF(acc[ma][1], a[ma], b[0][2], b[0][3]);
                MMABF(acc[ma][2], a[ma], b[1][0], b[1][1]);
                MMABF(acc[ma][3], a[ma], b[1][2], b[1][3]);
            }
        }
    }

    const int g = lane >> 2, tg = lane & 3;
    // direct stores: row-major
    #pragma unroll
    for (int ma = 0; ma < 4; ma++) {
        int r = rowBase + wm*64 + ma*16 + g;
        #pragma unroll
        for (int na = 0; na < 4; na++) {
            int c = colBase + wn*32 + na*8 + tg*2;
            *(float2*)&g_C[(size_t)r * NROW + c]     = make_float2(acc[ma][na][0], acc[ma][na][1]);
            *(float2*)&g_C[(size_t)(r+8) * NROW + c] = make_float2(acc[ma][na][2], acc[ma][na][3]);
        }
    }
    if (i != j) {
        // mirror via smem transpose: T[128][132]
        __syncthreads();
        float* T = (float*)smem;
        #pragma unroll
        for (int ma = 0; ma < 4; ma++) {
            int rl = wm*64 + ma*16 + g;
            #pragma unroll
            for (int na = 0; na < 4; na++) {
                int cl = wn*32 + na*8 + tg*2;
                T[(size_t)cl*132 + rl]         = acc[ma][na][0];
                T[(size_t)(cl+1)*132 + rl]     = acc[ma][na][1];
                T[(size_t)cl*132 + rl + 8]     = acc[ma][na][2];
                T[(size_t)(cl+1)*132 + rl + 8] = acc[ma][na][3];
            }
        }
        __syncthreads();
        #pragma unroll 1
        for (int s = 0; s < 16; s++) {
            int rr = wid + 8 * s;
            float4 v = *(const float4*)&T[(size_t)rr*132 + lane*4];
            *(float4*)&g_C[(size_t)(colBase + rr) * NROW + rowBase + lane*4] = v;
        }
    }
}

// ---------------- kernel: zero output ----------------
__global__ void k_zero(float4* __restrict__ out)
{
    const size_t n4 = (size_t)NROW * NROW / 4;
    const size_t stride = (size_t)gridDim.x * blockDim.x;
    for (size_t i = (size_t)blockIdx.x * blockDim.x + threadIdx.x; i < n4; i += stride)
        out[i] = make_float4(0.f, 0.f, 0.f, 0.f);
}

// ---------------- kernel: topk (radix on approx + exact fp32 rescore) ----------------
__global__ __launch_bounds__(256) void k_topk(float* __restrict__ out)
{
    __shared__ unsigned int sk[NROW];
    __shared__ unsigned int hist[256];
    __shared__ unsigned int s_pval;
    __shared__ int s_krem;
    __shared__ int s_ncand;
    __shared__ int   s_cidx[CAP];
    __shared__ float s_cval[CAP];

    const int row = blockIdx.x, tid = threadIdx.x;
    const int wid = tid >> 5, lane = tid & 31;
    const float* crow = g_C + (size_t)row * NROW;

    for (int v = tid; v < NROW / 4; v += 256) {
        float4 f = *(const float4*)(crow + v * 4);
        int c = v * 4;
        sk[c + 0] = enc_key(f.x); sk[c + 1] = enc_key(f.y);
        sk[c + 2] = enc_key(f.z); sk[c + 3] = enc_key(f.w);
    }
    __syncthreads();
    if (tid == 0) { sk[row] = 0u; s_pval = 0u; s_krem = KSEL; s_ncand = 0; }
    __syncthreads();

    // 4-level radix select for approx rank-49
    #pragma unroll
    for (int lvl = 0; lvl < 4; lvl++) {
        const int sh = 24 - 8 * lvl;
        hist[tid] = 0u;
        __syncthreads();
        const unsigned int pv = s_pval;
        const unsigned int pm = (lvl == 0) ? 0u : (0xFFFFFFFFu << (32 - 8 * lvl));
        for (int c = tid; c < NROW; c += 256) {
            unsigned int k = sk[c];
            bool ok = (k & pm) == pv;
            unsigned int bin = ok ? ((k >> sh) & 255u) : 0xffffffffu;
            unsigned int mm = __match_any_sync(0xffffffffu, bin);
            if (ok && ((__ffs(mm) - 1) == lane))
                atomicAdd(&hist[bin], __popc(mm));
        }
        __syncthreads();
        if (tid == 0) {
            int kr = s_krem;
            int b = 255;
            for (;; b--) {
                int cnt = (int)hist[b];
                if (kr <= cnt || b == 0) break;
                kr -= cnt;
            }
            s_krem = kr;
            s_pval = pv | ((unsigned int)b << sh);
        }
        __syncthreads();
    }

    // collect candidates: approx >= (rank49_val - MARGIN)
    const unsigned int tkey = enc_key(dec_key(s_pval) - MARGIN);
    for (int c = tid; c < NROW; c += 256) {
        if (sk[c] >= tkey) {
            int p = atomicAdd(&s_ncand, 1);
            if (p < CAP) s_cidx[p] = c;
        }
    }
    __syncthreads();
    const int nc = min(s_ncand, CAP);

    // exact fp32 rescore: warp per candidate
    const float* er = g_E + (size_t)row * DIM;
    for (int ii = wid; ii < nc; ii += 8) {
        const float* ec = g_E + (size_t)s_cidx[ii] * DIM;
        float s = 0.f;
        #pragma unroll
        for (int q = 0; q < 4; q++) {
            float4 a = *(const float4*)(er + lane * 16 + q * 4);
            float4 b = *(const float4*)(ec + lane * 16 + q * 4);
            s += a.x*b.x; s += a.y*b.y; s += a.z*b.z; s += a.w*b.w;
        }
        #pragma unroll
        for (int o = 16; o > 0; o >>= 1) s += __shfl_xor_sync(0xffffffffu, s, o);
        if (lane == 0) s_cval[ii] = s;
    }
    __syncthreads();

    // exact selection (stable: ties by lower index) + scatter
    for (int ii = tid; ii < nc; ii += 256) {
        float v = s_cval[ii];
        int c = s_cidx[ii];
        int rank = 0;
        for (int jj = 0; jj < nc; jj++) {
            float vj = s_cval[jj];
            rank += (vj > v) || (vj == v && s_cidx[jj] < c);
        }
        if (rank < KSEL) {
            out[(size_t)row * NROW + c] = v;
            out[(size_t)c * NROW + row] = v;
        }
    }
    if (tid == 0) out[(size_t)row * NROW + row] = 1.0f;
}

// ---------------- launcher ----------------
extern "C" void kernel_launch(void* const* d_in, const int* in_sizes, int n_in,
                              void* d_out, int out_size)
{
    (void)in_sizes; (void)n_in; (void)out_size;
    const float* Q  = (const float*)d_in[0];
    const float* sw = (const float*)d_in[1];

    cudaFuncSetAttribute(k_symgemm_bf, cudaFuncAttributeMaxDynamicSharedMemorySize, SMEM_SYM);

    k_combine<<<(DIM * DIM + 255) / 256, 256>>>(sw,
        (const float*)d_in[2], (const float*)d_in[4],
        (const float*)d_in[6], (const float*)d_in[8],
        (const float*)d_in[3], (const float*)d_in[5],
        (const float*)d_in[7], (const float*)d_in[9]);

    k_zero<<<4096, 256>>>((float4*)d_out);

    dim3 ge(DIM / TILE, NROW / TILE);          // (4, 64)
    k_gemmE<<<ge, 256>>>(Q);

    k_norm<<<NROW, 128>>>();

    k_splitbf<<<(NROW * DIM / 4) / 256, 256>>>();

    k_symgemm_bf<<<2080, 256, SMEM_SYM>>>();   // upper-tri 128x128 tiles (profiled: launch #6)

    k_topk<<<NROW, 256>>>((float*)d_out);
}

// round 6
// speedup vs baseline: 1.5225x; 1.1506x over previous
#include <cuda_runtime.h>
#include <cuda_fp16.h>
#include <cstdint>

#define NROW 8192
#define DIM  512
#define KSEL 49

/* ---- fp32 SIMT gemmE (R1 core) ---- */
#define TILE 128
#define KT   16
#define SPAD 132

/* ---- fp16 hi-only symgemm ---- */
#define KHB  1024              /* bytes per row: 512 fp16 */
#define CHB  128               /* chunk bytes = 64 fp16 */
#define NCH  8                 /* KHB / CHB */
#define ROWB 144               /* padded smem row bytes */
#define STG_BYTES (2*128*ROWB) /* 36864 */
#define SMEM_SYM  (3*STG_BYTES)/* 110592 */

#define MARGIN 2e-3f
#define CAP    3072

// ---------------- scratch ----------------
__device__ float  g_Wc[DIM*DIM];
__device__ float  g_bc[DIM];
__device__ float  g_E [(size_t)NROW*DIM];
__device__ __half g_Eh[(size_t)NROW*DIM];
__device__ __half g_Ch[(size_t)NROW*NROW];

// ---------------- helpers ----------------
__device__ __forceinline__ uint32_t smem_u32(const void* p) {
    uint32_t a;
    asm("{ .reg .u64 t; cvta.to.shared.u64 t, %1; cvt.u32.u64 %0, t; }" : "=r"(a) : "l"(p));
    return a;
}
__device__ __forceinline__ void cp16(uint32_t dst, const void* src) {
    asm volatile("cp.async.cg.shared.global [%0], [%1], 16;" :: "r"(dst), "l"(src));
}
#define CP_COMMIT() asm volatile("cp.async.commit_group;")
#define CP_WAIT(n)  asm volatile("cp.async.wait_group %0;" :: "n"(n))

#define LDSM4(r, addr) \
    asm volatile("ldmatrix.sync.aligned.m8n8.x4.shared.b16 {%0,%1,%2,%3}, [%4];" \
        : "=r"((r)[0]), "=r"((r)[1]), "=r"((r)[2]), "=r"((r)[3]) : "r"(addr))

#define MMAH(d, a, b0v, b1v) \
    asm volatile("mma.sync.aligned.m16n8k16.row.col.f32.f16.f16.f32 " \
        "{%0,%1,%2,%3}, {%4,%5,%6,%7}, {%8,%9}, {%0,%1,%2,%3};" \
        : "+f"((d)[0]), "+f"((d)[1]), "+f"((d)[2]), "+f"((d)[3]) \
        : "r"((a)[0]), "r"((a)[1]), "r"((a)[2]), "r"((a)[3]), "r"(b0v), "r"(b1v))

// packed f32x2 helpers (fp32 gemmE)
__device__ __forceinline__ unsigned long long ffma2(unsigned long long a,
                                                    unsigned long long b,
                                                    unsigned long long c) {
    unsigned long long d;
    asm("fma.rn.f32x2 %0, %1, %2, %3;" : "=l"(d) : "l"(a), "l"(b), "l"(c));
    return d;
}
__device__ __forceinline__ unsigned long long dup2(float x) {
    unsigned long long r; unsigned int u = __float_as_uint(x);
    asm("mov.b64 %0, {%1, %1};" : "=l"(r) : "r"(u));
    return r;
}
__device__ __forceinline__ unsigned long long pk2(float x, float y) {
    unsigned long long r;
    unsigned int ux = __float_as_uint(x), uy = __float_as_uint(y);
    asm("mov.b64 %0, {%1, %2};" : "=l"(r) : "r"(ux), "r"(uy));
    return r;
}
__device__ __forceinline__ float2 unpk(unsigned long long v) {
    unsigned int lo, hi;
    asm("mov.b64 {%0, %1}, %2;" : "=r"(lo), "=r"(hi) : "l"(v));
    float2 f; f.x = __uint_as_float(lo); f.y = __uint_as_float(hi);
    return f;
}
// 16-bit orderable keys for fp16 radix select
__device__ __forceinline__ unsigned int enc16(unsigned int u) {
    return ((u & 0x8000u) ? (~u) : (u | 0x8000u)) & 0xffffu;
}
__device__ __forceinline__ float dec16f(unsigned int k) {
    unsigned int u = (k & 0x8000u) ? (k & 0x7fffu) : ((~k) & 0xffffu);
    __half h = __ushort_as_half((unsigned short)u);
    return __half2float(h);
}

// ---------------- kernel: softmax + combine 4 projections ----------------
__global__ void k_combine(const float* __restrict__ sw,
    const float* __restrict__ W0, const float* __restrict__ W1,
    const float* __restrict__ W2, const float* __restrict__ W3,
    const float* __restrict__ b0, const float* __restrict__ b1,
    const float* __restrict__ b2, const float* __restrict__ b3)
{
    float a0 = sw[0], a1 = sw[1], a2 = sw[2], a3 = sw[3];
    float m  = fmaxf(fmaxf(a0, a1), fmaxf(a2, a3));
    float e0 = expf(a0 - m), e1 = expf(a1 - m), e2 = expf(a2 - m), e3 = expf(a3 - m);
    float inv = 1.0f / (e0 + e1 + e2 + e3);
    float w0 = e0 * inv, w1 = e1 * inv, w2 = e2 * inv, w3 = e3 * inv;
    int i = blockIdx.x * blockDim.x + threadIdx.x;
    if (i < DIM * DIM)
        g_Wc[i] = w0 * W0[i] + w1 * W1[i] + w2 * W2[i] + w3 * W3[i];
    if (i < DIM)
        g_bc[i] = w0 * b0[i] + w1 * b1[i] + w2 * b2[i] + w3 * b3[i];
}

// ---------------- fp32 SIMT gemm core (R1, proven) ----------------
template<int KDIM>
__device__ __forceinline__ void gemm_core(const float* __restrict__ A,
                                          const float* __restrict__ B,
                                          int rowBase, int colBase,
                                          int lda, int ldb,
                                          unsigned long long (&acc)[8][4])
{
    __shared__ float As[2][KT][SPAD];
    __shared__ float Bs[2][KT][SPAD];
    const int tid = threadIdx.x;
    const int tx = tid & 15, ty = tid >> 4;
    const int ri0 = ty * 8;
    const int c0  = tx * 4;
    float4 ra[2], rb[2];

    #pragma unroll
    for (int i = 0; i < 8; i++)
        #pragma unroll
        for (int j = 0; j < 4; j++) acc[i][j] = 0ull;

    auto loadG = [&](int k0) {
        #pragma unroll
        for (int l = 0; l < 2; l++) {
            int li = tid * 2 + l;
            int row = li >> 2, q = li & 3;
            ra[l] = *(const float4*)(A + (size_t)(rowBase + row) * lda + k0 + q * 4);
            rb[l] = *(const float4*)(B + (size_t)(colBase + row) * ldb + k0 + q * 4);
        }
    };
    auto storeS = [&](int buf) {
        #pragma unroll
        for (int l = 0; l < 2; l++) {
            int li = tid * 2 + l;
            int row = li >> 2, q = li & 3;
            As[buf][q*4+0][row] = ra[l].x; As[buf][q*4+1][row] = ra[l].y;
            As[buf][q*4+2][row] = ra[l].z; As[buf][q*4+3][row] = ra[l].w;
            Bs[buf][q*4+0][row] = rb[l].x; Bs[buf][q*4+1][row] = rb[l].y;
            Bs[buf][q*4+2][row] = rb[l].z; Bs[buf][q*4+3][row] = rb[l].w;
        }
    };

    loadG(0);
    storeS(0);
    __syncthreads();

    const int nk = KDIM / KT;
    for (int t = 0; t < nk; t++) {
        int buf = t & 1;
        if (t + 1 < nk) loadG((t + 1) * KT);
        #pragma unroll
        for (int kk = 0; kk < KT; kk++) {
            float4 a0 = *(const float4*)&As[buf][kk][ri0];
            float4 a1 = *(const float4*)&As[buf][kk][ri0 + 4];
            float4 b0 = *(const float4*)&Bs[buf][kk][c0];
            float4 b1 = *(const float4*)&Bs[buf][kk][64 + c0];
            unsigned long long bp[4];
            bp[0] = pk2(b0.x, b0.y); bp[1] = pk2(b0.z, b0.w);
            bp[2] = pk2(b1.x, b1.y); bp[3] = pk2(b1.z, b1.w);
            float av[8] = {a0.x, a0.y, a0.z, a0.w, a1.x, a1.y, a1.z, a1.w};
            #pragma unroll
            for (int i = 0; i < 8; i++) {
                unsigned long long ad = dup2(av[i]);
                #pragma unroll
                for (int j = 0; j < 4; j++)
                    acc[i][j] = ffma2(ad, bp[j], acc[i][j]);
            }
        }
        if (t + 1 < nk) storeS((t + 1) & 1);
        __syncthreads();
    }
}

// ---------------- kernel: E = Q @ Wc^T + bc (fp32 exact) ----------------
__global__ __launch_bounds__(256, 2) void k_gemmE(const float* __restrict__ Q)
{
    const int rowBase = blockIdx.y * TILE, colBase = blockIdx.x * TILE;
    unsigned long long acc[8][4];
    gemm_core<DIM>(Q, g_Wc, rowBase, colBase, DIM, DIM, acc);

    const int tid = threadIdx.x, tx = tid & 15, ty = tid >> 4;
    const int ri0 = ty * 8, c0 = tx * 4;
    float4 bias0 = *(const float4*)&g_bc[colBase + c0];
    float4 bias1 = *(const float4*)&g_bc[colBase + 64 + c0];
    #pragma unroll
    for (int i = 0; i < 8; i++) {
        float2 p0 = unpk(acc[i][0]), p1 = unpk(acc[i][1]);
        float2 p2 = unpk(acc[i][2]), p3 = unpk(acc[i][3]);
        size_t rbase = (size_t)(rowBase + ri0 + i) * DIM;
        *(float4*)(g_E + rbase + colBase + c0) =
            make_float4(p0.x + bias0.x, p0.y + bias0.y, p1.x + bias0.z, p1.y + bias0.w);
        *(float4*)(g_E + rbase + colBase + 64 + c0) =
            make_float4(p2.x + bias1.x, p2.y + bias1.y, p3.x + bias1.z, p3.y + bias1.w);
    }
}

// ---------------- kernel: L2-normalize rows of E ----------------
__global__ void k_norm()
{
    const int row = blockIdx.x, tid = threadIdx.x;  // 128 threads
    float4* e = (float4*)(g_E + (size_t)row * DIM);
    float4 v = e[tid];
    float ss = v.x*v.x + v.y*v.y + v.z*v.z + v.w*v.w;
    #pragma unroll
    for (int o = 16; o > 0; o >>= 1) ss += __shfl_xor_sync(0xffffffffu, ss, o);
    __shared__ float sred[4];
    if ((tid & 31) == 0) sred[tid >> 5] = ss;
    __syncthreads();
    float tot = sred[0] + sred[1] + sred[2] + sred[3];
    float s = 1.0f / fmaxf(sqrtf(tot), 1e-12f);
    v.x *= s; v.y *= s; v.z *= s; v.w *= s;
    e[tid] = v;
}

// ---------------- kernel: E -> fp16 ----------------
__global__ void k_split_h()
{
    int i = blockIdx.x * blockDim.x + threadIdx.x;   // one float4
    if (i >= NROW * DIM / 4) return;
    float4 s = ((const float4*)g_E)[i];
    __half2 h0 = __floats2half2_rn(s.x, s.y);
    __half2 h1 = __floats2half2_rn(s.z, s.w);
    uint2 w;
    w.x = *reinterpret_cast<uint32_t*>(&h0);
    w.y = *reinterpret_cast<uint32_t*>(&h1);
    ((uint2*)g_Eh)[i] = w;
}

// ---------------- kernel: approx C = H @ H^T (fp16), upper 128x128 tiles + mirror ----------------
__global__ __launch_bounds__(256, 2) void k_symgemm_h()
{
    extern __shared__ char smem[];
    // tile id -> (i, j), i <= j over 64x64 grid; prefix(j) = j(j+1)/2
    int t = blockIdx.x;
    int j = (int)((sqrtf(8.0f * (float)t + 1.0f) - 1.0f) * 0.5f);
    while ((j + 1) * (j + 2) / 2 <= t) j++;
    while (j * (j + 1) / 2 > t) j--;
    const int i = t - j * (j + 1) / 2;
    const int rowBase = i * TILE, colBase = j * TILE;

    const uint32_t sb = smem_u32(smem);
    const int tid = threadIdx.x, wid = tid >> 5, lane = tid & 31;
    const int wm = wid >> 2, wn = wid & 3;          // warp grid 2x4, warptile 64x32
    const int sel = lane >> 3, tl = lane & 7;

    const unsigned char* __restrict__ Eh = (const unsigned char*)g_Eh;

    auto load_stage = [&](int slot, int ch) {
        uint32_t base = sb + slot * STG_BYTES;
        #pragma unroll
        for (int u = 0; u < 4; u++) {
            int id = tid + 256 * u, row = id >> 3, cc = id & 7;
            cp16(base + row * ROWB + cc * 16,
                 Eh + (size_t)(rowBase + row) * KHB + ch * CHB + cc * 16);
        }
        #pragma unroll
        for (int u = 0; u < 4; u++) {
            int id = tid + 256 * u, row = id >> 3, cc = id & 7;
            cp16(base + 128 * ROWB + row * ROWB + cc * 16,
                 Eh + (size_t)(colBase + row) * KHB + ch * CHB + cc * 16);
        }
    };

    uint32_t aoff[4], boff[2];
    #pragma unroll
    for (int ma = 0; ma < 4; ma++)
        aoff[ma] = (uint32_t)((wm*64 + ma*16 + ((sel & 1) << 3) + tl) * ROWB + ((sel >> 1) << 4));
    #pragma unroll
    for (int np = 0; np < 2; np++)
        boff[np] = (uint32_t)(128*ROWB + (wn*32 + np*16 + ((sel >> 1) << 3) + tl) * ROWB + ((sel & 1) << 4));

    float acc[4][4][4];
    #pragma unroll
    for (int ma = 0; ma < 4; ma++)
        #pragma unroll
        for (int na = 0; na < 4; na++)
            #pragma unroll
            for (int q = 0; q < 4; q++) acc[ma][na][q] = 0.f;

    load_stage(0, 0); CP_COMMIT();
    load_stage(1, 1); CP_COMMIT();

    #pragma unroll 1
    for (int ch = 0; ch < NCH; ch++) {
        CP_WAIT(1);
        __syncthreads();
        if (ch + 2 < NCH) load_stage((ch + 2) % 3, ch + 2);
        CP_COMMIT();

        uint32_t sbase = sb + (ch % 3) * STG_BYTES;
        #pragma unroll
        for (int kk = 0; kk < 4; kk++) {
            uint32_t a[4][4], b[2][4];
            #pragma unroll
            for (int ma = 0; ma < 4; ma++) LDSM4(a[ma], sbase + aoff[ma] + kk * 32);
            #pragma unroll
            for (int np = 0; np < 2; np++) LDSM4(b[np], sbase + boff[np] + kk * 32);
            #pragma unroll
            for (int ma = 0; ma < 4; ma++) {
                MMAH(acc[ma][0], a[ma], b[0][0], b[0][1]);
                MMAH(acc[ma][1], a[ma], b[0][2], b[0][3]);
                MMAH(acc[ma][2], a[ma], b[1][0], b[1][1]);
                MMAH(acc[ma][3], a[ma], b[1][2], b[1][3]);
            }
        }
    }

    const int g = lane >> 2, tg = lane & 3;
    // direct stores: row-major fp16
    #pragma unroll
    for (int ma = 0; ma < 4; ma++) {
        int r = rowBase + wm*64 + ma*16 + g;
        #pragma unroll
        for (int na = 0; na < 4; na++) {
            int c = colBase + wn*32 + na*8 + tg*2;
            *(__half2*)&g_Ch[(size_t)r * NROW + c]     = __floats2half2_rn(acc[ma][na][0], acc[ma][na][1]);
            *(__half2*)&g_Ch[(size_t)(r+8) * NROW + c] = __floats2half2_rn(acc[ma][na][2], acc[ma][na][3]);
        }
    }
    if (i != j) {
        // mirror via smem transpose: T[128][132] floats
        __syncthreads();
        float* T = (float*)smem;
        #pragma unroll
        for (int ma = 0; ma < 4; ma++) {
            int rl = wm*64 + ma*16 + g;
            #pragma unroll
            for (int na = 0; na < 4; na++) {
                int cl = wn*32 + na*8 + tg*2;
                T[(size_t)cl*132 + rl]         = acc[ma][na][0];
                T[(size_t)(cl+1)*132 + rl]     = acc[ma][na][1];
                T[(size_t)cl*132 + rl + 8]     = acc[ma][na][2];
                T[(size_t)(cl+1)*132 + rl + 8] = acc[ma][na][3];
            }
        }
        __syncthreads();
        #pragma unroll 1
        for (int s = 0; s < 16; s++) {
            int rr = wid + 8 * s;
            float4 v = *(const float4*)&T[(size_t)rr*132 + lane*4];
            __half2 p0 = __floats2half2_rn(v.x, v.y);
            __half2 p1 = __floats2half2_rn(v.z, v.w);
            uint2 w;
            w.x = *reinterpret_cast<uint32_t*>(&p0);
            w.y = *reinterpret_cast<uint32_t*>(&p1);
            *(uint2*)&g_Ch[(size_t)(colBase + rr) * NROW + rowBase + lane*4] = w;
        }
    }
}

// ---------------- kernel: zero output ----------------
__global__ void k_zero(float4* __restrict__ out)
{
    const size_t n4 = (size_t)NROW * NROW / 4;
    const size_t stride = (size_t)gridDim.x * blockDim.x;
    for (size_t i = (size_t)blockIdx.x * blockDim.x + threadIdx.x; i < n4; i += stride)
        out[i] = make_float4(0.f, 0.f, 0.f, 0.f);
}

// ---------------- kernel: topk (2-level radix on fp16 approx + exact fp32 rescore) ----------------
__global__ __launch_bounds__(256) void k_topk(float* __restrict__ out)
{
    __shared__ unsigned short sk[NROW];     // 16 KB
    __shared__ unsigned int hist[256];
    __shared__ unsigned int s_pval;
    __shared__ int s_krem;
    __shared__ int s_ncand;
    __shared__ int   s_cidx[CAP];           // 12 KB
    __shared__ float s_cval[CAP];           // 12 KB

    const int row = blockIdx.x, tid = threadIdx.x;
    const int wid = tid >> 5, lane = tid & 31;
    const __half* crow = g_Ch + (size_t)row * NROW;

    for (int v = tid; v < NROW / 8; v += 256) {
        uint4 w = ((const uint4*)crow)[v];
        int c = v * 8;
        sk[c+0] = (unsigned short)enc16(w.x & 0xffffu);
        sk[c+1] = (unsigned short)enc16(w.x >> 16);
        sk[c+2] = (unsigned short)enc16(w.y & 0xffffu);
        sk[c+3] = (unsigned short)enc16(w.y >> 16);
        sk[c+4] = (unsigned short)enc16(w.z & 0xffffu);
        sk[c+5] = (unsigned short)enc16(w.z >> 16);
        sk[c+6] = (unsigned short)enc16(w.w & 0xffffu);
        sk[c+7] = (unsigned short)enc16(w.w >> 16);
    }
    __syncthreads();
    if (tid == 0) { sk[row] = 0; s_pval = 0u; s_krem = KSEL; s_ncand = 0; }
    __syncthreads();

    // 2-level 8-bit radix select for rank-49 among stored fp16 keys
    #pragma unroll
    for (int lvl = 0; lvl < 2; lvl++) {
        const int sh = 8 - 8 * lvl;
        hist[tid] = 0u;
        __syncthreads();
        const unsigned int pv = s_pval;
        const unsigned int pm = (lvl == 0) ? 0u : 0xFF00u;
        for (int c = tid; c < NROW; c += 256) {
            unsigned int k = sk[c];
            bool ok = (k & pm) == pv;
            unsigned int bin = ok ? ((k >> sh) & 255u) : 0xffffffffu;
            unsigned int mm = __match_any_sync(0xffffffffu, bin);
            if (ok && ((__ffs(mm) - 1) == lane))
                atomicAdd(&hist[bin], __popc(mm));
        }
        __syncthreads();
        if (tid == 0) {
            int kr = s_krem;
            int b = 255;
            for (;; b--) {
                int cnt = (int)hist[b];
                if (kr <= cnt || b == 0) break;
                kr -= cnt;
            }
            s_krem = kr;
            s_pval = pv | ((unsigned int)b << sh);
        }
        __syncthreads();
    }

    // collect candidates: approx >= rank49_val - MARGIN
    const float vth = dec16f(s_pval) - MARGIN;
    for (int c = tid; c < NROW; c += 256) {
        if (dec16f(sk[c]) >= vth && c != row) {
            int p = atomicAdd(&s_ncand, 1);
            if (p < CAP) s_cidx[p] = c;
        }
    }
    __syncthreads();
    const int nc = min(s_ncand, CAP);

    // exact fp32 rescore: warp per candidate
    const float* er = g_E + (size_t)row * DIM;
    for (int ii = wid; ii < nc; ii += 8) {
        const float* ec = g_E + (size_t)s_cidx[ii] * DIM;
        float s = 0.f;
        #pragma unroll
        for (int q = 0; q < 4; q++) {
            float4 a = *(const float4*)(er + lane * 16 + q * 4);
            float4 b = *(const float4*)(ec + lane * 16 + q * 4);
            s += a.x*b.x; s += a.y*b.y; s += a.z*b.z; s += a.w*b.w;
        }
        #pragma unroll
        for (int o = 16; o > 0; o >>= 1) s += __shfl_xor_sync(0xffffffffu, s, o);
        if (lane == 0) s_cval[ii] = s;
    }
    __syncthreads();

    // exact selection (ties by lower index) + symmetric scatter
    for (int ii = tid; ii < nc; ii += 256) {
        float v = s_cval[ii];
        int c = s_cidx[ii];
        int rank = 0;
        for (int jj = 0; jj < nc; jj++) {
            float vj = s_cval[jj];
            rank += (vj > v) || (vj == v && s_cidx[jj] < c);
        }
        if (rank < KSEL) {
            out[(size_t)row * NROW + c] = v;
            out[(size_t)c * NROW + row] = v;
        }
    }
    if (tid == 0) out[(size_t)row * NROW + row] = 1.0f;
}

// ---------------- launcher ----------------
extern "C" void kernel_launch(void* const* d_in, const int* in_sizes, int n_in,
                              void* d_out, int out_size)
{
    (void)in_sizes; (void)n_in; (void)out_size;
    const float* Q  = (const float*)d_in[0];
    const float* sw = (const float*)d_in[1];

    cudaFuncSetAttribute(k_symgemm_h, cudaFuncAttributeMaxDynamicSharedMemorySize, SMEM_SYM);

    k_combine<<<(DIM * DIM + 255) / 256, 256>>>(sw,
        (const float*)d_in[2], (const float*)d_in[4],
        (const float*)d_in[6], (const float*)d_in[8],
        (const float*)d_in[3], (const float*)d_in[5],
        (const float*)d_in[7], (const float*)d_in[9]);

    k_zero<<<4096, 256>>>((float4*)d_out);

    dim3 ge(DIM / TILE, NROW / TILE);          // (4, 64)
    k_gemmE<<<ge, 256>>>(Q);

    k_norm<<<NROW, 128>>>();

    k_split_h<<<(NROW * DIM / 4) / 256, 256>>>();

    k_symgemm_h<<<2080, 256, SMEM_SYM>>>();    // upper-tri 128x128 tiles

    k_topk<<<NROW, 256>>>((float*)d_out);
}

// round 7
// speedup vs baseline: 1.5656x; 1.0283x over previous
#include <cuda_runtime.h>
#include <cuda_fp16.h>
#include <cstdint>

#define NROW 8192
#define DIM  512
#define KSEL 49

/* ---- fp32 SIMT gemmE (R1 core) ---- */
#define TILE 128
#define KT   16
#define SPAD 132

/* ---- fp16 hi-only symgemm: 128x256 tiles ---- */
#define KHB  1024              /* bytes per row: 512 fp16 */
#define CHB  128               /* chunk bytes = 64 fp16 = 4 k16-steps */
#define NCH  8                 /* KHB / CHB */
#define ROWB 144               /* padded smem row bytes */
#define A_BY (128*ROWB)        /* 18432 */
#define B_BY (256*ROWB)        /* 36864 */
#define STG_BYTES (A_BY + B_BY)/* 55296 */
#define SMEM_SYM  (3*STG_BYTES)/* 165888 */

#define MARGIN 2e-3f
#define CAP    3072

// ---------------- scratch ----------------
__device__ float  g_Wc[DIM*DIM];
__device__ float  g_bc[DIM];
__device__ float  g_E [(size_t)NROW*DIM];
__device__ __half g_Eh[(size_t)NROW*DIM];
__device__ __half g_Ch[(size_t)NROW*NROW];

// ---------------- helpers ----------------
__device__ __forceinline__ uint32_t smem_u32(const void* p) {
    uint32_t a;
    asm("{ .reg .u64 t; cvta.to.shared.u64 t, %1; cvt.u32.u64 %0, t; }" : "=r"(a) : "l"(p));
    return a;
}
__device__ __forceinline__ void cp16(uint32_t dst, const void* src) {
    asm volatile("cp.async.cg.shared.global [%0], [%1], 16;" :: "r"(dst), "l"(src));
}
#define CP_COMMIT() asm volatile("cp.async.commit_group;")
#define CP_WAIT(n)  asm volatile("cp.async.wait_group %0;" :: "n"(n))

#define LDSM4(r, addr) \
    asm volatile("ldmatrix.sync.aligned.m8n8.x4.shared.b16 {%0,%1,%2,%3}, [%4];" \
        : "=r"((r)[0]), "=r"((r)[1]), "=r"((r)[2]), "=r"((r)[3]) : "r"(addr))

#define MMAH(d, a, b0v, b1v) \
    asm volatile("mma.sync.aligned.m16n8k16.row.col.f32.f16.f16.f32 " \
        "{%0,%1,%2,%3}, {%4,%5,%6,%7}, {%8,%9}, {%0,%1,%2,%3};" \
        : "+f"((d)[0]), "+f"((d)[1]), "+f"((d)[2]), "+f"((d)[3]) \
        : "r"((a)[0]), "r"((a)[1]), "r"((a)[2]), "r"((a)[3]), "r"(b0v), "r"(b1v))

// packed f32x2 helpers (fp32 gemmE)
__device__ __forceinline__ unsigned long long ffma2(unsigned long long a,
                                                    unsigned long long b,
                                                    unsigned long long c) {
    unsigned long long d;
    asm("fma.rn.f32x2 %0, %1, %2, %3;" : "=l"(d) : "l"(a), "l"(b), "l"(c));
    return d;
}
__device__ __forceinline__ unsigned long long dup2(float x) {
    unsigned long long r; unsigned int u = __float_as_uint(x);
    asm("mov.b64 %0, {%1, %1};" : "=l"(r) : "r"(u));
    return r;
}
__device__ __forceinline__ unsigned long long pk2(float x, float y) {
    unsigned long long r;
    unsigned int ux = __float_as_uint(x), uy = __float_as_uint(y);
    asm("mov.b64 %0, {%1, %2};" : "=l"(r) : "r"(ux), "r"(uy));
    return r;
}
__device__ __forceinline__ float2 unpk(unsigned long long v) {
    unsigned int lo, hi;
    asm("mov.b64 {%0, %1}, %2;" : "=r"(lo), "=r"(hi) : "l"(v));
    float2 f; f.x = __uint_as_float(lo); f.y = __uint_as_float(hi);
    return f;
}
// 16-bit orderable keys for fp16 radix select
__device__ __forceinline__ unsigned int enc16(unsigned int u) {
    return ((u & 0x8000u) ? (~u) : (u | 0x8000u)) & 0xffffu;
}
__device__ __forceinline__ float dec16f(unsigned int k) {
    unsigned int u = (k & 0x8000u) ? (k & 0x7fffu) : ((~k) & 0xffffu);
    __half h = __ushort_as_half((unsigned short)u);
    return __half2float(h);
}

// ---------------- kernel: softmax + combine 4 projections ----------------
__global__ void k_combine(const float* __restrict__ sw,
    const float* __restrict__ W0, const float* __restrict__ W1,
    const float* __restrict__ W2, const float* __restrict__ W3,
    const float* __restrict__ b0, const float* __restrict__ b1,
    const float* __restrict__ b2, const float* __restrict__ b3)
{
    float a0 = sw[0], a1 = sw[1], a2 = sw[2], a3 = sw[3];
    float m  = fmaxf(fmaxf(a0, a1), fmaxf(a2, a3));
    float e0 = expf(a0 - m), e1 = expf(a1 - m), e2 = expf(a2 - m), e3 = expf(a3 - m);
    float inv = 1.0f / (e0 + e1 + e2 + e3);
    float w0 = e0 * inv, w1 = e1 * inv, w2 = e2 * inv, w3 = e3 * inv;
    int i = blockIdx.x * blockDim.x + threadIdx.x;
    if (i < DIM * DIM)
        g_Wc[i] = w0 * W0[i] + w1 * W1[i] + w2 * W2[i] + w3 * W3[i];
    if (i < DIM)
        g_bc[i] = w0 * b0[i] + w1 * b1[i] + w2 * b2[i] + w3 * b3[i];
}

// ---------------- fp32 SIMT gemm core (R1, proven) ----------------
template<int KDIM>
__device__ __forceinline__ void gemm_core(const float* __restrict__ A,
                                          const float* __restrict__ B,
                                          int rowBase, int colBase,
                                          int lda, int ldb,
                                          unsigned long long (&acc)[8][4])
{
    __shared__ float As[2][KT][SPAD];
    __shared__ float Bs[2][KT][SPAD];
    const int tid = threadIdx.x;
    const int tx = tid & 15, ty = tid >> 4;
    const int ri0 = ty * 8;
    const int c0  = tx * 4;
    float4 ra[2], rb[2];

    #pragma unroll
    for (int i = 0; i < 8; i++)
        #pragma unroll
        for (int j = 0; j < 4; j++) acc[i][j] = 0ull;

    auto loadG = [&](int k0) {
        #pragma unroll
        for (int l = 0; l < 2; l++) {
            int li = tid * 2 + l;
            int row = li >> 2, q = li & 3;
            ra[l] = *(const float4*)(A + (size_t)(rowBase + row) * lda + k0 + q * 4);
            rb[l] = *(const float4*)(B + (size_t)(colBase + row) * ldb + k0 + q * 4);
        }
    };
    auto storeS = [&](int buf) {
        #pragma unroll
        for (int l = 0; l < 2; l++) {
            int li = tid * 2 + l;
            int row = li >> 2, q = li & 3;
            As[buf][q*4+0][row] = ra[l].x; As[buf][q*4+1][row] = ra[l].y;
            As[buf][q*4+2][row] = ra[l].z; As[buf][q*4+3][row] = ra[l].w;
            Bs[buf][q*4+0][row] = rb[l].x; Bs[buf][q*4+1][row] = rb[l].y;
            Bs[buf][q*4+2][row] = rb[l].z; Bs[buf][q*4+3][row] = rb[l].w;
        }
    };

    loadG(0);
    storeS(0);
    __syncthreads();

    const int nk = KDIM / KT;
    for (int t = 0; t < nk; t++) {
        int buf = t & 1;
        if (t + 1 < nk) loadG((t + 1) * KT);
        #pragma unroll
        for (int kk = 0; kk < KT; kk++) {
            float4 a0 = *(const float4*)&As[buf][kk][ri0];
            float4 a1 = *(const float4*)&As[buf][kk][ri0 + 4];
            float4 b0 = *(const float4*)&Bs[buf][kk][c0];
            float4 b1 = *(const float4*)&Bs[buf][kk][64 + c0];
            unsigned long long bp[4];
            bp[0] = pk2(b0.x, b0.y); bp[1] = pk2(b0.z, b0.w);
            bp[2] = pk2(b1.x, b1.y); bp[3] = pk2(b1.z, b1.w);
            float av[8] = {a0.x, a0.y, a0.z, a0.w, a1.x, a1.y, a1.z, a1.w};
            #pragma unroll
            for (int i = 0; i < 8; i++) {
                unsigned long long ad = dup2(av[i]);
                #pragma unroll
                for (int j = 0; j < 4; j++)
                    acc[i][j] = ffma2(ad, bp[j], acc[i][j]);
            }
        }
        if (t + 1 < nk) storeS((t + 1) & 1);
        __syncthreads();
    }
}

// ---------------- kernel: E = Q @ Wc^T + bc (fp32 exact) ----------------
__global__ __launch_bounds__(256, 2) void k_gemmE(const float* __restrict__ Q)
{
    const int rowBase = blockIdx.y * TILE, colBase = blockIdx.x * TILE;
    unsigned long long acc[8][4];
    gemm_core<DIM>(Q, g_Wc, rowBase, colBase, DIM, DIM, acc);

    const int tid = threadIdx.x, tx = tid & 15, ty = tid >> 4;
    const int ri0 = ty * 8, c0 = tx * 4;
    float4 bias0 = *(const float4*)&g_bc[colBase + c0];
    float4 bias1 = *(const float4*)&g_bc[colBase + 64 + c0];
    #pragma unroll
    for (int i = 0; i < 8; i++) {
        float2 p0 = unpk(acc[i][0]), p1 = unpk(acc[i][1]);
        float2 p2 = unpk(acc[i][2]), p3 = unpk(acc[i][3]);
        size_t rbase = (size_t)(rowBase + ri0 + i) * DIM;
        *(float4*)(g_E + rbase + colBase + c0) =
            make_float4(p0.x + bias0.x, p0.y + bias0.y, p1.x + bias0.z, p1.y + bias0.w);
        *(float4*)(g_E + rbase + colBase + 64 + c0) =
            make_float4(p2.x + bias1.x, p2.y + bias1.y, p3.x + bias1.z, p3.y + bias1.w);
    }
}

// ---------------- kernel: L2-normalize rows of E, write fp32 + fp16 ----------------
__global__ void k_norm()
{
    const int row = blockIdx.x, tid = threadIdx.x;  // 128 threads
    float4* e = (float4*)(g_E + (size_t)row * DIM);
    float4 v = e[tid];
    float ss = v.x*v.x + v.y*v.y + v.z*v.z + v.w*v.w;
    #pragma unroll
    for (int o = 16; o > 0; o >>= 1) ss += __shfl_xor_sync(0xffffffffu, ss, o);
    __shared__ float sred[4];
    if ((tid & 31) == 0) sred[tid >> 5] = ss;
    __syncthreads();
    float tot = sred[0] + sred[1] + sred[2] + sred[3];
    float s = 1.0f / fmaxf(sqrtf(tot), 1e-12f);
    v.x *= s; v.y *= s; v.z *= s; v.w *= s;
    e[tid] = v;
    __half2 h0 = __floats2half2_rn(v.x, v.y);
    __half2 h1 = __floats2half2_rn(v.z, v.w);
    uint2 w;
    w.x = *reinterpret_cast<uint32_t*>(&h0);
    w.y = *reinterpret_cast<uint32_t*>(&h1);
    ((uint2*)(g_Eh + (size_t)row * DIM))[tid] = w;
}

// ---------------- kernel: approx C = H @ H^T (fp16), 128x256 upper tiles + mirror ----------------
__global__ __launch_bounds__(256, 1) void k_symgemm_h()
{
    extern __shared__ char smem[];
    // tile id -> (i, j), i <= 2j+1 over 64 x 32 grid; prefix(j) = j^2 + j
    int t = blockIdx.x;
    int j = (int)((sqrtf(4.0f * (float)t + 1.0f) - 1.0f) * 0.5f);
    while ((j + 1) * (j + 1) + (j + 1) <= t) j++;
    while (j * j + j > t) j--;
    const int i = t - (j * j + j);
    const int rowBase = i * 128, colBase = j * 256;
    const bool overlap = (i == 2*j) || (i == 2*j + 1);   // tile straddles diagonal band

    const uint32_t sb = smem_u32(smem);
    const int tid = threadIdx.x, wid = tid >> 5, lane = tid & 31;
    const int wm = wid >> 2, wn = wid & 3;          // warp grid 2x4, warptile 64x64
    const int sel = lane >> 3, tl = lane & 7;

    const unsigned char* __restrict__ Eh = (const unsigned char*)g_Eh;

    auto load_stage = [&](int slot, int ch) {
        uint32_t base = sb + slot * STG_BYTES;
        #pragma unroll
        for (int u = 0; u < 4; u++) {
            int id = tid + 256 * u, row = id >> 3, cc = id & 7;
            cp16(base + row * ROWB + cc * 16,
                 Eh + (size_t)(rowBase + row) * KHB + ch * CHB + cc * 16);
        }
        #pragma unroll
        for (int u = 0; u < 8; u++) {
            int id = tid + 256 * u, row = id >> 3, cc = id & 7;
            cp16(base + A_BY + row * ROWB + cc * 16,
                 Eh + (size_t)(colBase + row) * KHB + ch * CHB + cc * 16);
        }
    };

    uint32_t aoff[4], boff[4];
    #pragma unroll
    for (int ma = 0; ma < 4; ma++)
        aoff[ma] = (uint32_t)((wm*64 + ma*16 + ((sel & 1) << 3) + tl) * ROWB + ((sel >> 1) << 4));
    #pragma unroll
    for (int np = 0; np < 4; np++)
        boff[np] = (uint32_t)(A_BY + (wn*64 + np*16 + ((sel >> 1) << 3) + tl) * ROWB + ((sel & 1) << 4));

    float acc[4][8][4];
    #pragma unroll
    for (int ma = 0; ma < 4; ma++)
        #pragma unroll
        for (int nn = 0; nn < 8; nn++)
            #pragma unroll
            for (int q = 0; q < 4; q++) acc[ma][nn][q] = 0.f;

    load_stage(0, 0); CP_COMMIT();
    load_stage(1, 1); CP_COMMIT();

    #pragma unroll 1
    for (int ch = 0; ch < NCH; ch++) {
        CP_WAIT(1);
        __syncthreads();
        if (ch + 2 < NCH) load_stage((ch + 2) % 3, ch + 2);
        CP_COMMIT();

        uint32_t sbase = sb + (ch % 3) * STG_BYTES;
        #pragma unroll
        for (int kk = 0; kk < 4; kk++) {
            uint32_t a[4][4], b[4][4];
            #pragma unroll
            for (int ma = 0; ma < 4; ma++) LDSM4(a[ma], sbase + aoff[ma] + kk * 32);
            #pragma unroll
            for (int np = 0; np < 4; np++) LDSM4(b[np], sbase + boff[np] + kk * 32);
            #pragma unroll
            for (int ma = 0; ma < 4; ma++)
                #pragma unroll
                for (int np = 0; np < 4; np++) {
                    MMAH(acc[ma][np*2],   a[ma], b[np][0], b[np][1]);
                    MMAH(acc[ma][np*2+1], a[ma], b[np][2], b[np][3]);
                }
        }
    }

    const int g = lane >> 2, tg = lane & 3;
    // direct stores: row-major fp16
    #pragma unroll
    for (int ma = 0; ma < 4; ma++) {
        int r = rowBase + wm*64 + ma*16 + g;
        #pragma unroll
        for (int nn = 0; nn < 8; nn++) {
            int c = colBase + wn*64 + nn*8 + tg*2;
            *(__half2*)&g_Ch[(size_t)r * NROW + c]     = __floats2half2_rn(acc[ma][nn][0], acc[ma][nn][1]);
            *(__half2*)&g_Ch[(size_t)(r+8) * NROW + c] = __floats2half2_rn(acc[ma][nn][2], acc[ma][nn][3]);
        }
    }
    // mirror via smem transpose: T[256][132] floats (benign identical-value race on overlap tiles)
    __syncthreads();
    float* T = (float*)smem;
    #pragma unroll
    for (int ma = 0; ma < 4; ma++) {
        int rl = wm*64 + ma*16 + g;
        #pragma unroll
        for (int nn = 0; nn < 8; nn++) {
            int cl = wn*64 + nn*8 + tg*2;
            T[(size_t)cl*132 + rl]         = acc[ma][nn][0];
            T[(size_t)(cl+1)*132 + rl]     = acc[ma][nn][1];
            T[(size_t)cl*132 + rl + 8]     = acc[ma][nn][2];
            T[(size_t)(cl+1)*132 + rl + 8] = acc[ma][nn][3];
        }
    }
    __syncthreads();
    (void)overlap;
    #pragma unroll 1
    for (int s = 0; s < 32; s++) {
        int rr = wid + 8 * s;
        float4 v = *(const float4*)&T[(size_t)rr*132 + lane*4];
        __half2 p0 = __floats2half2_rn(v.x, v.y);
        __half2 p1 = __floats2half2_rn(v.z, v.w);
        uint2 w;
        w.x = *reinterpret_cast<uint32_t*>(&p0);
        w.y = *reinterpret_cast<uint32_t*>(&p1);
        *(uint2*)&g_Ch[(size_t)(colBase + rr) * NROW + rowBase + lane*4] = w;
    }
}

// ---------------- kernel: zero output ----------------
__global__ void k_zero(float4* __restrict__ out)
{
    const size_t n4 = (size_t)NROW * NROW / 4;
    const size_t stride = (size_t)gridDim.x * blockDim.x;
    for (size_t i = (size_t)blockIdx.x * blockDim.x + threadIdx.x; i < n4; i += stride)
        out[i] = make_float4(0.f, 0.f, 0.f, 0.f);
}

// ---------------- kernel: topk (2-level radix on fp16 approx + exact fp32 rescore) ----------------
__global__ __launch_bounds__(256) void k_topk(float* __restrict__ out)
{
    __shared__ unsigned short sk[NROW];     // 16 KB
    __shared__ unsigned int hist[256];
    __shared__ unsigned int s_pval;
    __shared__ int s_krem;
    __shared__ int s_ncand;
    __shared__ int   s_cidx[CAP];           // 12 KB
    __shared__ float s_cval[CAP];           // 12 KB

    const int row = blockIdx.x, tid = threadIdx.x;
    const int wid = tid >> 5, lane = tid & 31;
    const __half* crow = g_Ch + (size_t)row * NROW;

    for (int v = tid; v < NROW / 8; v += 256) {
        uint4 w = ((const uint4*)crow)[v];
        int c = v * 8;
        sk[c+0] = (unsigned short)enc16(w.x & 0xffffu);
        sk[c+1] = (unsigned short)enc16(w.x >> 16);
        sk[c+2] = (unsigned short)enc16(w.y & 0xffffu);
        sk[c+3] = (unsigned short)enc16(w.y >> 16);
        sk[c+4] = (unsigned short)enc16(w.z & 0xffffu);
        sk[c+5] = (unsigned short)enc16(w.z >> 16);
        sk[c+6] = (unsigned short)enc16(w.w & 0xffffu);
        sk[c+7] = (unsigned short)enc16(w.w >> 16);
    }
    __syncthreads();
    if (tid == 0) { sk[row] = 0; s_pval = 0u; s_krem = KSEL; s_ncand = 0; }
    __syncthreads();

    // 2-level 8-bit radix select for rank-49 among stored fp16 keys
    #pragma unroll
    for (int lvl = 0; lvl < 2; lvl++) {
        const int sh = 8 - 8 * lvl;
        hist[tid] = 0u;
        __syncthreads();
        const unsigned int pv = s_pval;
        const unsigned int pm = (lvl == 0) ? 0u : 0xFF00u;
        for (int c = tid; c < NROW; c += 256) {
            unsigned int k = sk[c];
            bool ok = (k & pm) == pv;
            unsigned int bin = ok ? ((k >> sh) & 255u) : 0xffffffffu;
            unsigned int mm = __match_any_sync(0xffffffffu, bin);
            if (ok && ((__ffs(mm) - 1) == lane))
                atomicAdd(&hist[bin], __popc(mm));
        }
        __syncthreads();
        if (tid == 0) {
            int kr = s_krem;
            int b = 255;
            for (;; b--) {
                int cnt = (int)hist[b];
                if (kr <= cnt || b == 0) break;
                kr -= cnt;
            }
            s_krem = kr;
            s_pval = pv | ((unsigned int)b << sh);
        }
        __syncthreads();
    }

    // collect candidates: approx >= rank49_val - MARGIN
    const float vth = dec16f(s_pval) - MARGIN;
    for (int c = tid; c < NROW; c += 256) {
        if (dec16f(sk[c]) >= vth && c != row) {
            int p = atomicAdd(&s_ncand, 1);
            if (p < CAP) s_cidx[p] = c;
        }
    }
    __syncthreads();
    const int nc = min(s_ncand, CAP);

    // exact fp32 rescore: warp per candidate, lane-coalesced reads
    const float* er = g_E + (size_t)row * DIM;
    for (int ii = wid; ii < nc; ii += 8) {
        const float* ec = g_E + (size_t)s_cidx[ii] * DIM;
        float s = 0.f;
        #pragma unroll
        for (int q = 0; q < 4; q++) {
            float4 a = *(const float4*)(er + q * 128 + lane * 4);
            float4 b = *(const float4*)(ec + q * 128 + lane * 4);
            s += a.x*b.x; s += a.y*b.y; s += a.z*b.z; s += a.w*b.w;
        }
        #pragma unroll
        for (int o = 16; o > 0; o >>= 1) s += __shfl_xor_sync(0xffffffffu, s, o);
        if (lane == 0) s_cval[ii] = s;
    }
    __syncthreads();

    // exact selection (ties by lower index) + symmetric scatter
    for (int ii = tid; ii < nc; ii += 256) {
        float v = s_cval[ii];
        int c = s_cidx[ii];
        int rank = 0;
        for (int jj = 0; jj < nc; jj++) {
            float vj = s_cval[jj];
            rank += (vj > v) || (vj == v && s_cidx[jj] < c);
        }
        if (rank < KSEL) {
            out[(size_t)row * NROW + c] = v;
            out[(size_t)c * NROW + row] = v;
        }
    }
    if (tid == 0) out[(size_t)row * NROW + row] = 1.0f;
}

// ---------------- launcher ----------------
extern "C" void kernel_launch(void* const* d_in, const int* in_sizes, int n_in,
                              void* d_out, int out_size)
{
    (void)in_sizes; (void)n_in; (void)out_size;
    const float* Q  = (const float*)d_in[0];
    const float* sw = (const float*)d_in[1];

    cudaFuncSetAttribute(k_symgemm_h, cudaFuncAttributeMaxDynamicSharedMemorySize, SMEM_SYM);

    // launch order chosen so k_symgemm_h is launch #3 (the one ncu captures)
    k_combine<<<(DIM * DIM + 255) / 256, 256>>>(sw,
        (const float*)d_in[2], (const float*)d_in[4],
        (const float*)d_in[6], (const float*)d_in[8],
        (const float*)d_in[3], (const float*)d_in[5],
        (const float*)d_in[7], (const float*)d_in[9]);

    dim3 ge(DIM / TILE, NROW / TILE);          // (4, 64)
    k_gemmE<<<ge, 256>>>(Q);

    k_norm<<<NROW, 128>>>();                   // also emits fp16 E

    k_symgemm_h<<<1056, 256, SMEM_SYM>>>();    // 128x256 upper-band tiles + mirror

    k_zero<<<4096, 256>>>((float4*)d_out);

    k_topk<<<NROW, 256>>>((float*)d_out);
}